// round 15
// baseline (speedup 1.0000x reference)
#include <cuda_runtime.h>
#include <cuda_bf16.h>

#define NNN     16384
#define MODIN   113
#define MODOUT  57

typedef unsigned long long u64;

#define OUT_H    16384
#define OUT_MSG  (OUT_H + 4194304)
#define OUT_HEB  (OUT_MSG + 4194304)

// per (b,n) scratch row of 64: [0:25) sigmoids (decay@24), [25:57) prim_new.
// After K2a, [0:32) is overwritten with recv.
__device__ float g_scr[(size_t)8 * NNN * 64];

__device__ __forceinline__ u64 pk2(float w) {
    u64 r; asm("mov.b64 %0, {%1, %1};" : "=l"(r) : "f"(w)); return r;
}
__device__ __forceinline__ void fma2(u64 &a, u64 b, u64 c) {
    asm("fma.rn.f32x2 %0, %1, %2, %0;" : "+l"(a) : "l"(b), "l"(c));
}
__device__ __forceinline__ void upk2(u64 v, float &lo, float &hi) {
    asm("mov.b64 {%0,%1}, %2;" : "=f"(lo), "=f"(hi) : "l"(v));
}
__device__ __forceinline__ float mytanh(float x) {
    float e = __expf(2.0f * x);
    return 1.0f - __fdividef(2.0f, e + 1.0f);
}
__device__ __forceinline__ float sigm(float x) {
    return __fdividef(1.0f, 1.0f + __expf(-x));
}
__device__ __forceinline__ unsigned smem_u32(const void* p) {
    return (unsigned)__cvta_generic_to_shared(p);
}
__device__ __forceinline__ void cpasync16(unsigned saddr, const void* g) {
    asm volatile("cp.async.cg.shared.global [%0], [%1], 16;" :: "r"(saddr), "l"(g));
}
__device__ __forceinline__ void cp_commit() {
    asm volatile("cp.async.commit_group;");
}
template<int N> __device__ __forceinline__ void cp_wait() {
    asm volatile("cp.async.wait_group %0;" :: "n"(N));
}

// psum-writing partial GEMV; x via LDS.128 broadcast (padded psum slots)
__device__ __forceinline__ void gemv_part(const float* __restrict__ W, int iStride,
                                          const float* __restrict__ X,
                                          float* __restrict__ ps,
                                          int kbeg, int kend)
{
    u64 a0 = 0, a1 = 0, a2 = 0, a3 = 0;
    const float* w = W + kbeg * iStride;
    const ulonglong2* x = (const ulonglong2*)(X + kbeg * 8);
#pragma unroll 4
    for (int i = kbeg; i < kend; ++i) {
        u64 wp = pk2(*w); w += iStride;
        ulonglong2 v0 = x[0], v1 = x[1]; x += 2;
        fma2(a0, wp, v0.x); fma2(a1, wp, v0.y);
        fma2(a2, wp, v1.x); fma2(a3, wp, v1.y);
    }
    *(u64*)(ps)     = a0;
    *(u64*)(ps + 2) = a1;
    *(u64*)(ps + 4) = a2;
    *(u64*)(ps + 6) = a3;
}

// full-K GEMV, lane owns ONE output row (8 packed batches)
__device__ __forceinline__ void gemv1(const float* __restrict__ W,
                                      const float* __restrict__ X,
                                      int K, u64* A)
{
    u64 a0 = 0, a1 = 0, a2 = 0, a3 = 0;
    const ulonglong2* x = (const ulonglong2*)X;
#pragma unroll 4
    for (int i = 0; i < K; ++i) {
        u64 wp = pk2(W[i]);
        ulonglong2 v0 = x[0], v1 = x[1]; x += 2;
        fma2(a0, wp, v0.x); fma2(a1, wp, v0.y);
        fma2(a2, wp, v1.x); fma2(a3, wp, v1.y);
    }
    A[0] = a0; A[1] = a1; A[2] = a2; A[3] = a3;
}

// full-K GEMV, lane owns TWO output rows
__device__ __forceinline__ void gemv2(const float* __restrict__ W0,
                                      const float* __restrict__ W1,
                                      const float* __restrict__ X,
                                      int K, u64* A)
{
    u64 a0=0,a1=0,a2=0,a3=0,a4=0,a5=0,a6=0,a7=0;
    const ulonglong2* x = (const ulonglong2*)X;
#pragma unroll 4
    for (int i = 0; i < K; ++i) {
        u64 p0 = pk2(W0[i]), p1 = pk2(W1[i]);
        ulonglong2 v0 = x[0], v1 = x[1]; x += 2;
        fma2(a0, p0, v0.x); fma2(a1, p0, v0.y);
        fma2(a2, p0, v1.x); fma2(a3, p0, v1.y);
        fma2(a4, p1, v0.x); fma2(a5, p1, v0.y);
        fma2(a6, p1, v1.x); fma2(a7, p1, v1.y);
    }
    A[0]=a0; A[1]=a1; A[2]=a2; A[3]=a3;
    A[4]=a4; A[5]=a5; A[6]=a6; A[7]=a7;
}

// tanh(bias + acc) for 8 packed values -> 2 float4 stores
__device__ __forceinline__ void act_store(float* dst, const u64* A, float bias)
{
    float lo, hi; float4 f0, f1;
    upk2(A[0], lo, hi); f0.x = mytanh(bias + lo); f0.y = mytanh(bias + hi);
    upk2(A[1], lo, hi); f0.z = mytanh(bias + lo); f0.w = mytanh(bias + hi);
    upk2(A[2], lo, hi); f1.x = mytanh(bias + lo); f1.y = mytanh(bias + hi);
    upk2(A[3], lo, hi); f1.z = mytanh(bias + lo); f1.w = mytanh(bias + hi);
    ((float4*)dst)[0] = f0; ((float4*)dst)[1] = f1;
}

// =================== K1: per-neuron modulator MLP (unchanged R14) ===================
#define K1_W1  0
#define K1_W2  3616
#define K1_X   5440
#define K1_H   6344
#define K1_PS  6600
#define K1_TOT 9160

__global__ void __launch_bounds__(256, 6)
modk(const float* __restrict__ hin,  const float* __restrict__ dlog,
     const float* __restrict__ prim, const float* __restrict__ trc,
     const float* __restrict__ modw1, const float* __restrict__ modb1g,
     const float* __restrict__ modw2, const float* __restrict__ modb2g,
     const float* __restrict__ nidg)
{
    __shared__ float s[K1_TOT];
    const int tid = threadIdx.x, wid = tid >> 5, lane = tid & 31;
    const int n = blockIdx.x;

    {
        unsigned sW1 = smem_u32(s + K1_W1);
        const float4* g1 = (const float4*)(modw1 + (size_t)n * (32*MODIN));
        for (int i = tid; i < 904; i += 256)
            cpasync16(sW1 + i*16, g1 + i);
        cp_commit();
        unsigned sW2 = smem_u32(s + K1_W2);
        const float4* g2 = (const float4*)(modw2 + (size_t)n * (32*MODOUT));
        for (int i = tid; i < 456; i += 256)
            cpasync16(sW2 + i*16, g2 + i);
        cp_commit();
    }

    {
        int b = wid;
        size_t nb = (size_t)b * NNN + n;
        s[K1_X + (16+lane)*8 + b] = hin[nb*32 + lane];
        s[K1_X + (49+lane)*8 + b] = prim[nb*32 + lane];
        s[K1_X + (81+lane)*8 + b] = nidg[(size_t)n*32 + lane];
        if (lane < 16) s[K1_X + lane*8 + b] = trc[nb*16 + lane];
        if (lane == 0) s[K1_X + 48*8 + b] = dlog[nb];
    }
    cp_wait<1>();
    __syncthreads();

    {
        int kb = (113*wid) >> 3, ke = (113*(wid+1)) >> 3;
        gemv_part(s + K1_W1 + lane*MODIN, 1, s + K1_X,
                  s + K1_PS + (wid*32 + lane)*10, kb, ke);
    }
    __syncthreads();
    {
        int o = tid >> 3, b = tid & 7;
        float t = modb1g[n*32 + o];
#pragma unroll
        for (int w = 0; w < 8; w++) t += s[K1_PS + (w*32 + o)*10 + b];
        s[K1_H + tid] = mytanh(t);
    }
    cp_wait<0>();
    __syncthreads();

    {
        int oh = wid & 1, kseg = wid >> 1;
        int o = oh*32 + lane;
        if (oh == 0 || lane < 25)
            gemv_part(s + K1_W2 + o, MODOUT, s + K1_H,
                      s + K1_PS + (wid*32 + lane)*10, kseg*8, kseg*8 + 8);
    }
    __syncthreads();

    for (int v = tid; v < 456; v += 256) {
        int o = v >> 3, b = v & 7;
        int oh = o >> 5, ol = o & 31;
        float t = modb2g[n*57 + o];
#pragma unroll
        for (int ks = 0; ks < 4; ks++)
            t += s[K1_PS + ((oh + 2*ks)*32 + ol)*10 + b];
        float val = (o < 25) ? sigm(t) : (t + s[K1_X + (49 + (o-25))*8 + b]);
        g_scr[((size_t)b*NNN + n)*64 + o] = val;
    }
}

// =================== K2a: gather + state MLP (24 warps/SM) ===================
#define A_SW1  0        // 64 x 97
#define A_SW2  6208     // 32 x 65 pad
#define A_SB1  8288
#define A_SB2  8352
#define A_WS   8384
#define AW_SG    776
#define AW_ICONI 976
#define AW_IBRDI 992
#define AW_SH    1000
#define AWSN     1512
#define KA_WARPS 24
#define KA_THREADS (KA_WARPS*32)
#define KA_FLOATS (A_WS + KA_WARPS*AWSN)
#define KA_BYTES  (KA_FLOATS*4)
#define GRID_KA 148
#define TOT_AW (GRID_KA*KA_WARPS)

__global__ void __launch_bounds__(KA_THREADS, 1)
cellK2a(const float* __restrict__ ccs, const float* __restrict__ hin,
        const float* __restrict__ pm,
        const float* __restrict__ sw1g, const float* __restrict__ sb1g,
        const float* __restrict__ sw2g, const float* __restrict__ sb2g,
        const int*   __restrict__ conn, const int* __restrict__ bconn,
        float* __restrict__ outp)
{
    extern __shared__ float smf[];
    const int tid  = threadIdx.x;
    const int wid  = tid >> 5;
    const int lane = tid & 31;

    for (int i = tid; i < 1552; i += KA_THREADS)
        ((float4*)(smf + A_SW1))[i] = ((const float4*)sw1g)[i];
    for (int i = tid; i < 2048; i += KA_THREADS) {
        int d = i >> 6, h2 = i & 63;
        smf[A_SW2 + d*65 + h2] = sw2g[i];
    }
    if (tid < 64) smf[A_SB1 + tid] = sb1g[tid];
    if (tid >= 64 && tid < 96) smf[A_SB2 + tid - 64] = sb2g[tid - 64];
    __syncthreads();

    float* ws = smf + A_WS + wid*AWSN;
    int*   wi = (int*)ws;
    const int gwarp = blockIdx.x*KA_WARPS + wid;

    for (int n = gwarp; n < NNN; n += TOT_AW) {
        const int nc = n >> 8, c = n & 255;
        const bool isb = (c >= 4 && c < 20);

        if (lane < 16) wi[AW_ICONI + lane] = conn[n*16 + lane];
        if (isb && lane < 8) wi[AW_IBRDI + lane] = bconn[(nc*16 + (c-4))*8 + lane];
        {
            float hv[8], pv[8], sg[8];
#pragma unroll
            for (int b = 0; b < 8; b++) {
                size_t nb = (size_t)b * NNN + n;
                hv[b] = hin[nb*32 + lane];
                pv[b] = g_scr[nb*64 + 25 + lane];
                if (lane < 25) sg[b] = g_scr[nb*64 + lane];
            }
            ((float4*)(ws + lane*8))[0] = make_float4(hv[0],hv[1],hv[2],hv[3]);
            ((float4*)(ws + lane*8))[1] = make_float4(hv[4],hv[5],hv[6],hv[7]);
            ((float4*)(ws + (64+lane)*8))[0] = make_float4(pv[0],pv[1],pv[2],pv[3]);
            ((float4*)(ws + (64+lane)*8))[1] = make_float4(pv[4],pv[5],pv[6],pv[7]);
            if (lane < 25) {
                ((float4*)(ws + AW_SG + lane*8))[0] = make_float4(sg[0],sg[1],sg[2],sg[3]);
                ((float4*)(ws + AW_SG + lane*8))[1] = make_float4(sg[4],sg[5],sg[6],sg[7]);
                if (lane == 24) {
                    ((float4*)(ws + 96*8))[0] = make_float4(sg[0],sg[1],sg[2],sg[3]);
                    ((float4*)(ws + 96*8))[1] = make_float4(sg[4],sg[5],sg[6],sg[7]);
                }
            }
        }
        __syncwarp();

        // gather -> X rows 32-63 + writeback recv to g_scr[0:32) (sig region now dead)
        {
            float acc[8];
#pragma unroll
            for (int b = 0; b < 8; b++) {
                size_t bb = (size_t)b * NNN;
                float a = (c < 4) ? ccs[b*2048 + nc*32 + lane] : 0.0f;
#pragma unroll
                for (int k = 0; k < 16; k++) {
                    int ci = wi[AW_ICONI + k];
                    a = fmaf(pm[(bb + nc*256 + ci)*32 + lane], ws[AW_SG + k*8 + b], a);
                }
                if (isb) {
#pragma unroll
                    for (int k = 0; k < 8; k++) {
                        int bi = wi[AW_IBRDI + k];
                        a = fmaf(pm[(bb + (bi>>4)*256 + 4 + (bi&15))*32 + lane],
                                 ws[AW_SG + (16+k)*8 + b], a);
                    }
                }
                acc[b] = a;
                g_scr[(bb + n)*64 + lane] = a;
            }
            ((float4*)(ws + (32+lane)*8))[0] = make_float4(acc[0],acc[1],acc[2],acc[3]);
            ((float4*)(ws + (32+lane)*8))[1] = make_float4(acc[4],acc[5],acc[6],acc[7]);
        }
        __syncwarp();

        // state l1 O=64 K=97
        {
            u64 A[8];
            gemv2(smf + A_SW1 + lane*97, smf + A_SW1 + (lane+32)*97, ws, 97, A);
            act_store(ws + AW_SH + lane*8,      A,     smf[A_SB1 + lane]);
            act_store(ws + AW_SH + (lane+32)*8, A + 4, smf[A_SB1 + lane + 32]);
        }
        __syncwarp();

        // state l2 O=32 K=64 -> h_new to outp
        {
            u64 B[4];
            gemv1(smf + A_SW2 + lane*65, ws + AW_SH, 64, B);
            float dh[8];
            upk2(B[0], dh[0], dh[1]); upk2(B[1], dh[2], dh[3]);
            upk2(B[2], dh[4], dh[5]); upk2(B[3], dh[6], dh[7]);
            float sb = smf[A_SB2 + lane];
#pragma unroll
            for (int b = 0; b < 8; b++) {
                float dec = ws[96*8 + b];
                float hv  = ws[lane*8 + b];
                float hn  = dec*hv + (1.0f - dec)*mytanh(dh[b] + sb);
                outp[OUT_H + ((size_t)b*NNN + n)*32 + lane] = hn;
            }
        }
        __syncwarp();
    }
}

// =================== K2b: msg MLP (24 warps/SM) ===================
#define B_MW1  0        // 64 x 97 (96 used)
#define B_MW2  6208     // 32 x 65 pad
#define B_MB1  8288
#define B_MB2  8352
#define B_WS   8384
#define BW_SH  768
#define BWSN   1280
#define KB_WARPS 24
#define KB_THREADS (KB_WARPS*32)
#define KB_FLOATS (B_WS + KB_WARPS*BWSN)
#define KB_BYTES  (KB_FLOATS*4)
#define GRID_KB 148
#define TOT_BW (GRID_KB*KB_WARPS)

__global__ void __launch_bounds__(KB_THREADS, 1)
cellK2b(const float* __restrict__ mw1g, const float* __restrict__ mb1g,
        const float* __restrict__ mw2g, const float* __restrict__ mb2g,
        const float* __restrict__ nidg,
        float* __restrict__ outp)
{
    extern __shared__ float smf[];
    const int tid  = threadIdx.x;
    const int wid  = tid >> 5;
    const int lane = tid & 31;

    for (int i = tid; i < 6144; i += KB_THREADS) {
        int hh = i / 96, ii = i - hh*96;
        smf[B_MW1 + hh*97 + ii] = mw1g[i];
    }
    for (int i = tid; i < 2048; i += KB_THREADS) {
        int d = i >> 6, h2 = i & 63;
        smf[B_MW2 + d*65 + h2] = mw2g[i];
    }
    if (tid < 64) smf[B_MB1 + tid] = mb1g[tid];
    if (tid >= 64 && tid < 96) smf[B_MB2 + tid - 64] = mb2g[tid - 64];
    __syncthreads();

    float* ws = smf + B_WS + wid*BWSN;
    const int gwarp = blockIdx.x*KB_WARPS + wid;

    for (int n = gwarp; n < NNN; n += TOT_BW) {
        // X = [h_new | recv | nid]
        float nidv = nidg[(size_t)n*32 + lane];
        {
            float hv[8], rv[8];
#pragma unroll
            for (int b = 0; b < 8; b++) {
                size_t nb = (size_t)b * NNN + n;
                hv[b] = outp[OUT_H + nb*32 + lane];
                rv[b] = g_scr[nb*64 + lane];
            }
            ((float4*)(ws + lane*8))[0] = make_float4(hv[0],hv[1],hv[2],hv[3]);
            ((float4*)(ws + lane*8))[1] = make_float4(hv[4],hv[5],hv[6],hv[7]);
            ((float4*)(ws + (32+lane)*8))[0] = make_float4(rv[0],rv[1],rv[2],rv[3]);
            ((float4*)(ws + (32+lane)*8))[1] = make_float4(rv[4],rv[5],rv[6],rv[7]);
            float4 nf = make_float4(nidv, nidv, nidv, nidv);
            ((float4*)(ws + (64+lane)*8))[0] = nf;
            ((float4*)(ws + (64+lane)*8))[1] = nf;
        }
        __syncwarp();

        // msg l1 O=64 K=96
        {
            u64 A[8];
            gemv2(smf + B_MW1 + lane*97, smf + B_MW1 + (lane+32)*97, ws, 96, A);
            act_store(ws + BW_SH + lane*8,      A,     smf[B_MB1 + lane]);
            act_store(ws + BW_SH + (lane+32)*8, A + 4, smf[B_MB1 + lane + 32]);
        }
        __syncwarp();

        // msg l2 O=32 K=64 -> STG msg
        {
            u64 B[4];
            gemv1(smf + B_MW2 + lane*65, ws + BW_SH, 64, B);
            float dm[8];
            upk2(B[0], dm[0], dm[1]); upk2(B[1], dm[2], dm[3]);
            upk2(B[2], dm[4], dm[5]); upk2(B[3], dm[6], dm[7]);
            float mb = smf[B_MB2 + lane];
#pragma unroll
            for (int b = 0; b < 8; b++)
                outp[OUT_MSG + ((size_t)b*NNN + n)*32 + lane] = mytanh(dm[b] + mb);
        }
        __syncwarp();
    }
}

// ---------------- kernel B: hebbian + readout (unchanged) ----------------
#define BSTR 36
#define SMEMB_BYTES ((256*BSTR + 4096)*4)

__global__ void __launch_bounds__(512, 2)
cellB_kernel(const int* __restrict__ conn,
             const float* __restrict__ trc,
             float* __restrict__ outp)
{
    extern __shared__ float smb[];
    float* ms = smb;
    int*   cs = (int*)(smb + 256*BSTR);
    const int b  = blockIdx.x >> 6;
    const int nc = blockIdx.x & 63;
    const int tid = threadIdx.x;

    const float* msgg = outp + OUT_MSG + ((size_t)b*NNN + nc*256) * 32;
    for (int i = tid; i < 8192; i += 512)
        ms[(i >> 5)*BSTR + (i & 31)] = msgg[i];
    const int4* cg = (const int4*)(conn + nc*4096);
    for (int i = tid; i < 1024; i += 512) ((int4*)cs)[i] = cg[i];
    __syncthreads();

    const int c  = tid >> 1;
    const int kh = tid & 1;
    float4 me4[8];
#pragma unroll
    for (int j = 0; j < 8; j++) me4[j] = ((const float4*)(ms + c*BSTR))[j];

    const size_t base = (size_t)b*NNN + nc*256 + c;
    float4 t4[2];
    t4[0] = ((const float4*)(trc + base*16 + kh*8))[0];
    t4[1] = ((const float4*)(trc + base*16 + kh*8))[1];

    float heb[8];
#pragma unroll
    for (int k = 0; k < 8; k++) {
        int ci = cs[c*16 + kh*8 + k];
        const float4* nb = (const float4*)(ms + ci*BSTR);
        float a0 = 0.0f, a1 = 0.0f, a2 = 0.0f, a3 = 0.0f;
#pragma unroll
        for (int j = 0; j < 8; j += 2) {
            float4 v0 = nb[j], v1 = nb[j+1];
            a0 = fmaf(me4[j].x,   v0.x, a0);
            a1 = fmaf(me4[j].y,   v0.y, a1);
            a2 = fmaf(me4[j].z,   v0.z, a2);
            a3 = fmaf(me4[j].w,   v0.w, a3);
            a0 = fmaf(me4[j+1].x, v1.x, a0);
            a1 = fmaf(me4[j+1].y, v1.y, a1);
            a2 = fmaf(me4[j+1].z, v1.z, a2);
            a3 = fmaf(me4[j+1].w, v1.w, a3);
        }
        heb[k] = ((a0 + a1) + (a2 + a3)) * 0.003125f;
    }
    float4* h4 = (float4*)(outp + OUT_HEB + base*16 + kh*8);
    h4[0] = make_float4(fmaf(0.9f,t4[0].x,heb[0]), fmaf(0.9f,t4[0].y,heb[1]),
                        fmaf(0.9f,t4[0].z,heb[2]), fmaf(0.9f,t4[0].w,heb[3]));
    h4[1] = make_float4(fmaf(0.9f,t4[1].x,heb[4]), fmaf(0.9f,t4[1].y,heb[5]),
                        fmaf(0.9f,t4[1].z,heb[6]), fmaf(0.9f,t4[1].w,heb[7]));

    if (tid < 32) {
        float r = 0.25f * (ms[252*BSTR + tid] + ms[253*BSTR + tid] +
                           ms[254*BSTR + tid] + ms[255*BSTR + tid]);
        outp[b*2048 + nc*32 + tid] = r;
    }
}

extern "C" void kernel_launch(void* const* d_in, const int* in_sizes, int n_in,
                              void* d_out, int out_size)
{
    const float* ccs   = (const float*)d_in[0];
    const float* hin   = (const float*)d_in[1];
    const float* pm    = (const float*)d_in[2];
    const float* dlog  = (const float*)d_in[3];
    const float* prim  = (const float*)d_in[4];
    const float* trc   = (const float*)d_in[5];
    const float* sw1   = (const float*)d_in[6];
    const float* sb1   = (const float*)d_in[7];
    const float* sw2   = (const float*)d_in[8];
    const float* sb2   = (const float*)d_in[9];
    const float* mw1   = (const float*)d_in[10];
    const float* mb1   = (const float*)d_in[11];
    const float* mw2   = (const float*)d_in[12];
    const float* mb2   = (const float*)d_in[13];
    const float* modw1 = (const float*)d_in[14];
    const float* modb1 = (const float*)d_in[15];
    const float* modw2 = (const float*)d_in[16];
    const float* modb2 = (const float*)d_in[17];
    const float* nid   = (const float*)d_in[18];
    const int*   conn  = (const int*)d_in[19];
    const int*   bconn = (const int*)d_in[20];
    float* outp = (float*)d_out;

    cudaFuncSetAttribute(cellK2a, cudaFuncAttributeMaxDynamicSharedMemorySize, KA_BYTES);
    cudaFuncSetAttribute(cellK2b, cudaFuncAttributeMaxDynamicSharedMemorySize, KB_BYTES);
    cudaFuncSetAttribute(cellB_kernel, cudaFuncAttributeMaxDynamicSharedMemorySize, SMEMB_BYTES);

    modk<<<NNN, 256>>>(hin, dlog, prim, trc, modw1, modb1, modw2, modb2, nid);

    cellK2a<<<GRID_KA, KA_THREADS, KA_BYTES>>>(
        ccs, hin, pm, sw1, sb1, sw2, sb2, conn, bconn, outp);

    cellK2b<<<GRID_KB, KB_THREADS, KB_BYTES>>>(
        mw1, mb1, mw2, mb2, nid, outp);

    cellB_kernel<<<512, 512, SMEMB_BYTES>>>(conn, trc, outp);
}

// round 16
// speedup vs baseline: 1.1146x; 1.1146x over previous
#include <cuda_runtime.h>
#include <cuda_bf16.h>

#define NNN     16384
#define MODIN   113
#define MODOUT  57

typedef unsigned long long u64;

#define OUT_H    16384
#define OUT_MSG  (OUT_H + 4194304)
#define OUT_HEB  (OUT_MSG + 4194304)

// per (b,n) scratch row of 64: [0:25) sigmoids (16 conn, 8 border, decay@24), [25:57) prim_new
__device__ float g_scr[(size_t)8 * NNN * 64];

__device__ __forceinline__ u64 pk2(float w) {
    u64 r; asm("mov.b64 %0, {%1, %1};" : "=l"(r) : "f"(w)); return r;
}
__device__ __forceinline__ void fma2(u64 &a, u64 b, u64 c) {
    asm("fma.rn.f32x2 %0, %1, %2, %0;" : "+l"(a) : "l"(b), "l"(c));
}
__device__ __forceinline__ void upk2(u64 v, float &lo, float &hi) {
    asm("mov.b64 {%0,%1}, %2;" : "=f"(lo), "=f"(hi) : "l"(v));
}
__device__ __forceinline__ float mytanh(float x) {
    float e = __expf(2.0f * x);
    return 1.0f - __fdividef(2.0f, e + 1.0f);
}
__device__ __forceinline__ float sigm(float x) {
    return __fdividef(1.0f, 1.0f + __expf(-x));
}
__device__ __forceinline__ unsigned smem_u32(const void* p) {
    return (unsigned)__cvta_generic_to_shared(p);
}
__device__ __forceinline__ void cpasync16(unsigned saddr, const void* g) {
    asm volatile("cp.async.cg.shared.global [%0], [%1], 16;" :: "r"(saddr), "l"(g));
}
__device__ __forceinline__ void cp_commit() {
    asm volatile("cp.async.commit_group;");
}
template<int N> __device__ __forceinline__ void cp_wait() {
    asm volatile("cp.async.wait_group %0;" :: "n"(N));
}

// psum-writing partial GEMV; x via LDS.128 broadcast (padded psum slots)
__device__ __forceinline__ void gemv_part(const float* __restrict__ W, int iStride,
                                          const float* __restrict__ X,
                                          float* __restrict__ ps,
                                          int kbeg, int kend)
{
    u64 a0 = 0, a1 = 0, a2 = 0, a3 = 0;
    const float* w = W + kbeg * iStride;
    const ulonglong2* x = (const ulonglong2*)(X + kbeg * 8);
#pragma unroll 4
    for (int i = kbeg; i < kend; ++i) {
        u64 wp = pk2(*w); w += iStride;
        ulonglong2 v0 = x[0], v1 = x[1]; x += 2;
        fma2(a0, wp, v0.x); fma2(a1, wp, v0.y);
        fma2(a2, wp, v1.x); fma2(a3, wp, v1.y);
    }
    *(u64*)(ps)     = a0;
    *(u64*)(ps + 2) = a1;
    *(u64*)(ps + 4) = a2;
    *(u64*)(ps + 6) = a3;
}

// full-K GEMV, lane owns ONE output row (8 packed batches)
__device__ __forceinline__ void gemv1(const float* __restrict__ W,
                                      const float* __restrict__ X,
                                      int K, u64* A)
{
    u64 a0 = 0, a1 = 0, a2 = 0, a3 = 0;
    const ulonglong2* x = (const ulonglong2*)X;
#pragma unroll 4
    for (int i = 0; i < K; ++i) {
        u64 wp = pk2(W[i]);
        ulonglong2 v0 = x[0], v1 = x[1]; x += 2;
        fma2(a0, wp, v0.x); fma2(a1, wp, v0.y);
        fma2(a2, wp, v1.x); fma2(a3, wp, v1.y);
    }
    A[0] = a0; A[1] = a1; A[2] = a2; A[3] = a3;
}

// full-K GEMV, lane owns TWO output rows
__device__ __forceinline__ void gemv2(const float* __restrict__ W0,
                                      const float* __restrict__ W1,
                                      const float* __restrict__ X,
                                      int K, u64* A)
{
    u64 a0=0,a1=0,a2=0,a3=0,a4=0,a5=0,a6=0,a7=0;
    const ulonglong2* x = (const ulonglong2*)X;
#pragma unroll 4
    for (int i = 0; i < K; ++i) {
        u64 p0 = pk2(W0[i]), p1 = pk2(W1[i]);
        ulonglong2 v0 = x[0], v1 = x[1]; x += 2;
        fma2(a0, p0, v0.x); fma2(a1, p0, v0.y);
        fma2(a2, p0, v1.x); fma2(a3, p0, v1.y);
        fma2(a4, p1, v0.x); fma2(a5, p1, v0.y);
        fma2(a6, p1, v1.x); fma2(a7, p1, v1.y);
    }
    A[0]=a0; A[1]=a1; A[2]=a2; A[3]=a3;
    A[4]=a4; A[5]=a5; A[6]=a6; A[7]=a7;
}

// tanh(bias + acc) for 8 packed values -> 2 float4 stores
__device__ __forceinline__ void act_store(float* dst, const u64* A, float bias)
{
    float lo, hi; float4 f0, f1;
    upk2(A[0], lo, hi); f0.x = mytanh(bias + lo); f0.y = mytanh(bias + hi);
    upk2(A[1], lo, hi); f0.z = mytanh(bias + lo); f0.w = mytanh(bias + hi);
    upk2(A[2], lo, hi); f1.x = mytanh(bias + lo); f1.y = mytanh(bias + hi);
    upk2(A[3], lo, hi); f1.z = mytanh(bias + lo); f1.w = mytanh(bias + hi);
    ((float4*)dst)[0] = f0; ((float4*)dst)[1] = f1;
}

// =================== K1: per-neuron modulator MLP (256 thr, cp.async) ===================
#define K1_W1  0
#define K1_W2  3616
#define K1_X   5440
#define K1_H   6344
#define K1_PS  6600
#define K1_TOT 9160

__global__ void __launch_bounds__(256, 6)
modk(const float* __restrict__ hin,  const float* __restrict__ dlog,
     const float* __restrict__ prim, const float* __restrict__ trc,
     const float* __restrict__ modw1, const float* __restrict__ modb1g,
     const float* __restrict__ modw2, const float* __restrict__ modb2g,
     const float* __restrict__ nidg)
{
    __shared__ float s[K1_TOT];
    const int tid = threadIdx.x, wid = tid >> 5, lane = tid & 31;
    const int n = blockIdx.x;

    {
        unsigned sW1 = smem_u32(s + K1_W1);
        const float4* g1 = (const float4*)(modw1 + (size_t)n * (32*MODIN));
        for (int i = tid; i < 904; i += 256)
            cpasync16(sW1 + i*16, g1 + i);
        cp_commit();
        unsigned sW2 = smem_u32(s + K1_W2);
        const float4* g2 = (const float4*)(modw2 + (size_t)n * (32*MODOUT));
        for (int i = tid; i < 456; i += 256)
            cpasync16(sW2 + i*16, g2 + i);
        cp_commit();
    }

    {
        int b = wid;
        size_t nb = (size_t)b * NNN + n;
        s[K1_X + (16+lane)*8 + b] = hin[nb*32 + lane];
        s[K1_X + (49+lane)*8 + b] = prim[nb*32 + lane];
        s[K1_X + (81+lane)*8 + b] = nidg[(size_t)n*32 + lane];
        if (lane < 16) s[K1_X + lane*8 + b] = trc[nb*16 + lane];
        if (lane == 0) s[K1_X + 48*8 + b] = dlog[nb];
    }
    cp_wait<1>();
    __syncthreads();

    {
        int kb = (113*wid) >> 3, ke = (113*(wid+1)) >> 3;
        gemv_part(s + K1_W1 + lane*MODIN, 1, s + K1_X,
                  s + K1_PS + (wid*32 + lane)*10, kb, ke);
    }
    __syncthreads();
    {
        int o = tid >> 3, b = tid & 7;
        float t = modb1g[n*32 + o];
#pragma unroll
        for (int w = 0; w < 8; w++) t += s[K1_PS + (w*32 + o)*10 + b];
        s[K1_H + tid] = mytanh(t);
    }
    cp_wait<0>();
    __syncthreads();

    {
        int oh = wid & 1, kseg = wid >> 1;
        int o = oh*32 + lane;
        if (oh == 0 || lane < 25)
            gemv_part(s + K1_W2 + o, MODOUT, s + K1_H,
                      s + K1_PS + (wid*32 + lane)*10, kseg*8, kseg*8 + 8);
    }
    __syncthreads();

    for (int v = tid; v < 456; v += 256) {
        int o = v >> 3, b = v & 7;
        int oh = o >> 5, ol = o & 31;
        float t = modb2g[n*57 + o];
#pragma unroll
        for (int ks = 0; ks < 4; ks++)
            t += s[K1_PS + ((oh + 2*ks)*32 + ol)*10 + b];
        float val = (o < 25) ? sigm(t) : (t + s[K1_X + (49 + (o-25))*8 + b]);
        g_scr[((size_t)b*NNN + n)*64 + o] = val;
    }
}

// =================== K2: warp-per-neuron gather + state/msg MLPs (R14) ===================
#define OFF_SW1   0
#define OFF_SW2   6208
#define OFF_MW1   8288
#define OFF_MW2   14496
#define OFF_SB1   16576
#define OFF_SB2   16640
#define OFF_MB1   16672
#define OFF_MB2   16736
#define WS_BASE   16768
#define W_SG    776
#define W_ICONI 976
#define W_IBRDI 992
#define W_SH    1000
#define WSN     1512
#define K2_WARPS 7
#define K2_THREADS (K2_WARPS*32)
#define K2_FLOATS (WS_BASE + K2_WARPS*WSN)
#define K2_BYTES  (K2_FLOATS*4)
#define GRID_K2 296
#define TOT_WARPS (GRID_K2*K2_WARPS)

__global__ void __launch_bounds__(K2_THREADS, 2)
cellK2(const float* __restrict__ ccs, const float* __restrict__ hin,
       const float* __restrict__ pm,
       const float* __restrict__ sw1g, const float* __restrict__ sb1g,
       const float* __restrict__ sw2g, const float* __restrict__ sb2g,
       const float* __restrict__ mw1g, const float* __restrict__ mb1g,
       const float* __restrict__ mw2g, const float* __restrict__ mb2g,
       const float* __restrict__ nidg,
       const int*   __restrict__ conn, const int* __restrict__ bconn,
       float* __restrict__ outp)
{
    extern __shared__ float smf[];
    const int tid  = threadIdx.x;
    const int wid  = tid >> 5;
    const int lane = tid & 31;

    for (int i = tid; i < 1552; i += K2_THREADS)
        ((float4*)(smf + OFF_SW1))[i] = ((const float4*)sw1g)[i];
    for (int i = tid; i < 2048; i += K2_THREADS) {
        int d = i >> 6, h2 = i & 63;
        smf[OFF_SW2 + d*65 + h2] = sw2g[i];
        smf[OFF_MW2 + d*65 + h2] = mw2g[i];
    }
    for (int i = tid; i < 6144; i += K2_THREADS) {
        int hh = i / 96, ii = i - hh*96;
        smf[OFF_MW1 + hh*97 + ii] = mw1g[i];
    }
    if (tid < 64) smf[OFF_SB1 + tid] = sb1g[tid];
    if (tid < 32) smf[OFF_SB2 + tid] = sb2g[tid];
    if (tid >= 64 && tid < 128) smf[OFF_MB1 + tid - 64] = mb1g[tid - 64];
    if (tid >= 32 && tid < 64) smf[OFF_MB2 + tid - 32] = mb2g[tid - 32];
    __syncthreads();

    float* ws = smf + WS_BASE + wid*WSN;
    int*   wi = (int*)ws;

    const int gwarp = blockIdx.x*K2_WARPS + wid;

    for (int n = gwarp; n < NNN; n += TOT_WARPS) {
        const int nc = n >> 8, c = n & 255;
        const bool isb = (c >= 4 && c < 20);

        if (lane < 16) wi[W_ICONI + lane] = conn[n*16 + lane];
        if (isb && lane < 8) wi[W_IBRDI + lane] = bconn[(nc*16 + (c-4))*8 + lane];
        float nidv = nidg[(size_t)n*32 + lane];
        {
            float hv[8], pv[8], sg[8];
#pragma unroll
            for (int b = 0; b < 8; b++) {
                size_t nb = (size_t)b * NNN + n;
                hv[b] = hin[nb*32 + lane];
                pv[b] = g_scr[nb*64 + 25 + lane];
                if (lane < 25) sg[b] = g_scr[nb*64 + lane];
            }
            ((float4*)(ws + lane*8))[0] = make_float4(hv[0],hv[1],hv[2],hv[3]);
            ((float4*)(ws + lane*8))[1] = make_float4(hv[4],hv[5],hv[6],hv[7]);
            ((float4*)(ws + (64+lane)*8))[0] = make_float4(pv[0],pv[1],pv[2],pv[3]);
            ((float4*)(ws + (64+lane)*8))[1] = make_float4(pv[4],pv[5],pv[6],pv[7]);
            if (lane < 25) {
                ((float4*)(ws + W_SG + lane*8))[0] = make_float4(sg[0],sg[1],sg[2],sg[3]);
                ((float4*)(ws + W_SG + lane*8))[1] = make_float4(sg[4],sg[5],sg[6],sg[7]);
                if (lane == 24) {
                    ((float4*)(ws + 96*8))[0] = make_float4(sg[0],sg[1],sg[2],sg[3]);
                    ((float4*)(ws + 96*8))[1] = make_float4(sg[4],sg[5],sg[6],sg[7]);
                }
            }
        }
        __syncwarp();

        {
            float acc[8];
#pragma unroll
            for (int b = 0; b < 8; b++) {
                size_t bb = (size_t)b * NNN;
                float a = (c < 4) ? ccs[b*2048 + nc*32 + lane] : 0.0f;
#pragma unroll
                for (int k = 0; k < 16; k++) {
                    int ci = wi[W_ICONI + k];
                    a = fmaf(pm[(bb + nc*256 + ci)*32 + lane], ws[W_SG + k*8 + b], a);
                }
                if (isb) {
#pragma unroll
                    for (int k = 0; k < 8; k++) {
                        int bi = wi[W_IBRDI + k];
                        a = fmaf(pm[(bb + (bi>>4)*256 + 4 + (bi&15))*32 + lane],
                                 ws[W_SG + (16+k)*8 + b], a);
                    }
                }
                acc[b] = a;
            }
            ((float4*)(ws + (32+lane)*8))[0] = make_float4(acc[0],acc[1],acc[2],acc[3]);
            ((float4*)(ws + (32+lane)*8))[1] = make_float4(acc[4],acc[5],acc[6],acc[7]);
        }
        __syncwarp();

        {
            u64 A[8];
            gemv2(smf + OFF_SW1 + lane*97, smf + OFF_SW1 + (lane+32)*97, ws, 97, A);
            act_store(ws + W_SH + lane*8,      A,     smf[OFF_SB1 + lane]);
            act_store(ws + W_SH + (lane+32)*8, A + 4, smf[OFF_SB1 + lane + 32]);
        }
        __syncwarp();

        {
            u64 B[4];
            gemv1(smf + OFF_SW2 + lane*65, ws + W_SH, 64, B);
            float dh[8];
            upk2(B[0], dh[0], dh[1]); upk2(B[1], dh[2], dh[3]);
            upk2(B[2], dh[4], dh[5]); upk2(B[3], dh[6], dh[7]);
            float sb = smf[OFF_SB2 + lane];
            float hn[8];
#pragma unroll
            for (int b = 0; b < 8; b++) {
                float dec = ws[96*8 + b];
                float hv  = ws[lane*8 + b];
                hn[b] = dec*hv + (1.0f - dec)*mytanh(dh[b] + sb);
                outp[OUT_H + ((size_t)b*NNN + n)*32 + lane] = hn[b];
            }
            ((float4*)(ws + lane*8))[0] = make_float4(hn[0],hn[1],hn[2],hn[3]);
            ((float4*)(ws + lane*8))[1] = make_float4(hn[4],hn[5],hn[6],hn[7]);
            float4 nf = make_float4(nidv, nidv, nidv, nidv);
            ((float4*)(ws + (64+lane)*8))[0] = nf;
            ((float4*)(ws + (64+lane)*8))[1] = nf;
        }
        __syncwarp();

        {
            u64 A[8];
            gemv2(smf + OFF_MW1 + lane*97, smf + OFF_MW1 + (lane+32)*97, ws, 96, A);
            act_store(ws + W_SH + lane*8,      A,     smf[OFF_MB1 + lane]);
            act_store(ws + W_SH + (lane+32)*8, A + 4, smf[OFF_MB1 + lane + 32]);
        }
        __syncwarp();

        {
            u64 B[4];
            gemv1(smf + OFF_MW2 + lane*65, ws + W_SH, 64, B);
            float dm[8];
            upk2(B[0], dm[0], dm[1]); upk2(B[1], dm[2], dm[3]);
            upk2(B[2], dm[4], dm[5]); upk2(B[3], dm[6], dm[7]);
            float mb = smf[OFF_MB2 + lane];
#pragma unroll
            for (int b = 0; b < 8; b++)
                outp[OUT_MSG + ((size_t)b*NNN + n)*32 + lane] = mytanh(dm[b] + mb);
        }
        __syncwarp();
    }
}

// ---------------- kernel B: hebbian + readout (grid 2048, 4 thr/neuron) ----------------
#define BSTR 36
#define SMEMB_BYTES ((256*BSTR + 1024)*4)

__global__ void __launch_bounds__(256, 5)
cellB_kernel(const int* __restrict__ conn,
             const float* __restrict__ trc,
             float* __restrict__ outp)
{
    extern __shared__ float smb[];
    float* ms = smb;                    // full 256 x 36 msg tile
    int*   cs = (int*)(smb + 256*BSTR); // 1024 ints (this quarter's conn)
    const int b  = blockIdx.x >> 8;
    const int nc = (blockIdx.x >> 2) & 63;
    const int q  = blockIdx.x & 3;
    const int tid = threadIdx.x;

    const float* msgg = outp + OUT_MSG + ((size_t)b*NNN + nc*256) * 32;
    for (int i = tid; i < 8192; i += 256)
        ms[(i >> 5)*BSTR + (i & 31)] = msgg[i];
    {
        const int4* cg = (const int4*)(conn + nc*4096 + q*1024);
        ((int4*)cs)[tid] = cg[tid];
    }
    __syncthreads();

    const int cl = tid >> 2;          // local neuron 0..63
    const int c  = q*64 + cl;
    const int kq = tid & 3;           // k-quarter: [kq*4, kq*4+4)
    float4 me4[8];
#pragma unroll
    for (int j = 0; j < 8; j++) me4[j] = ((const float4*)(ms + c*BSTR))[j];

    const size_t base = (size_t)b*NNN + nc*256 + c;
    float4 t4 = ((const float4*)(trc + base*16 + kq*4))[0];

    float heb[4];
#pragma unroll
    for (int k = 0; k < 4; k++) {
        int ci = cs[cl*16 + kq*4 + k];
        const float4* nb = (const float4*)(ms + ci*BSTR);
        float a0 = 0.0f, a1 = 0.0f, a2 = 0.0f, a3 = 0.0f;
#pragma unroll
        for (int j = 0; j < 8; j += 2) {
            float4 v0 = nb[j], v1 = nb[j+1];
            a0 = fmaf(me4[j].x,   v0.x, a0);
            a1 = fmaf(me4[j].y,   v0.y, a1);
            a2 = fmaf(me4[j].z,   v0.z, a2);
            a3 = fmaf(me4[j].w,   v0.w, a3);
            a0 = fmaf(me4[j+1].x, v1.x, a0);
            a1 = fmaf(me4[j+1].y, v1.y, a1);
            a2 = fmaf(me4[j+1].z, v1.z, a2);
            a3 = fmaf(me4[j+1].w, v1.w, a3);
        }
        heb[k] = ((a0 + a1) + (a2 + a3)) * 0.003125f;
    }
    float4* h4 = (float4*)(outp + OUT_HEB + base*16 + kq*4);
    h4[0] = make_float4(fmaf(0.9f,t4.x,heb[0]), fmaf(0.9f,t4.y,heb[1]),
                        fmaf(0.9f,t4.z,heb[2]), fmaf(0.9f,t4.w,heb[3]));

    if (q == 3 && tid < 32) {
        float r = 0.25f * (ms[252*BSTR + tid] + ms[253*BSTR + tid] +
                           ms[254*BSTR + tid] + ms[255*BSTR + tid]);
        outp[b*2048 + nc*32 + tid] = r;
    }
}

extern "C" void kernel_launch(void* const* d_in, const int* in_sizes, int n_in,
                              void* d_out, int out_size)
{
    const float* ccs   = (const float*)d_in[0];
    const float* hin   = (const float*)d_in[1];
    const float* pm    = (const float*)d_in[2];
    const float* dlog  = (const float*)d_in[3];
    const float* prim  = (const float*)d_in[4];
    const float* trc   = (const float*)d_in[5];
    const float* sw1   = (const float*)d_in[6];
    const float* sb1   = (const float*)d_in[7];
    const float* sw2   = (const float*)d_in[8];
    const float* sb2   = (const float*)d_in[9];
    const float* mw1   = (const float*)d_in[10];
    const float* mb1   = (const float*)d_in[11];
    const float* mw2   = (const float*)d_in[12];
    const float* mb2   = (const float*)d_in[13];
    const float* modw1 = (const float*)d_in[14];
    const float* modb1 = (const float*)d_in[15];
    const float* modw2 = (const float*)d_in[16];
    const float* modb2 = (const float*)d_in[17];
    const float* nid   = (const float*)d_in[18];
    const int*   conn  = (const int*)d_in[19];
    const int*   bconn = (const int*)d_in[20];
    float* outp = (float*)d_out;

    cudaFuncSetAttribute(cellK2, cudaFuncAttributeMaxDynamicSharedMemorySize, K2_BYTES);
    cudaFuncSetAttribute(cellB_kernel, cudaFuncAttributeMaxDynamicSharedMemorySize, SMEMB_BYTES);

    modk<<<NNN, 256>>>(hin, dlog, prim, trc, modw1, modb1, modw2, modb2, nid);

    cellK2<<<GRID_K2, K2_THREADS, K2_BYTES>>>(
        ccs, hin, pm, sw1, sb1, sw2, sb2, mw1, mb1, mw2, mb2,
        nid, conn, bconn, outp);

    cellB_kernel<<<2048, 256, SMEMB_BYTES>>>(conn, trc, outp);
}